// round 4
// baseline (speedup 1.0000x reference)
#include <cuda_runtime.h>
#include <cstdint>

#define RESP 32
#define RESF 64
#define NP   8192
#define NF   65536
#define CH   128
#define EPSV 1e-5f

// ---- scratch (device globals: allocation-free rule) ----
__device__ int   g_pg[RESP*RESP*RESP];
__device__ float g_h1[NP*CH];
__device__ float g_out1[NF*CH];
__device__ float g_h2[NF*CH];
__device__ float g_M1s[64*CH*CH];   // aggregated conv1 weights, [mat][n][k], tf32-rounded
__device__ float g_W2s[27*CH*CH];   // conv2 weights, [mat][n][k], tf32-rounded
__device__ float g_sum[32], g_sq[32];
__device__ float g_ps[32][32], g_pq[32][32];

// ================= helpers =================
__device__ __forceinline__ uint32_t smem_u32(const void* p) {
    uint32_t a;
    asm("{ .reg .u64 t; cvta.to.shared.u64 t, %1; cvt.u32.u64 %0, t; }" : "=r"(a) : "l"(p));
    return a;
}
__device__ __forceinline__ float tf32r(float x) {
    uint32_t u;
    asm("cvt.rna.tf32.f32 %0, %1;" : "=r"(u) : "f"(x));
    return __uint_as_float(u);
}
__device__ __forceinline__ void cp16(uint32_t dst, const void* src, uint32_t ssz) {
    asm volatile("cp.async.cg.shared.global [%0], [%1], 16, %2;" :: "r"(dst), "l"(src), "r"(ssz));
}
__device__ __forceinline__ void cp_commit() { asm volatile("cp.async.commit_group;"); }
#define CP_WAIT(n) asm volatile("cp.async.wait_group %0;" :: "n"(n) : "memory")

__device__ __forceinline__ void ldsm4(uint32_t* r, uint32_t addr) {
    asm volatile("ldmatrix.sync.aligned.m8n8.x4.shared.b16 {%0,%1,%2,%3}, [%4];"
        : "=r"(r[0]), "=r"(r[1]), "=r"(r[2]), "=r"(r[3]) : "r"(addr));
}
__device__ __forceinline__ void mma_tf32(float* d, const uint32_t* a, const uint32_t* b) {
    asm volatile("mma.sync.aligned.m16n8k8.row.col.f32.tf32.tf32.f32 "
        "{%0,%1,%2,%3}, {%4,%5,%6,%7}, {%8,%9}, {%0,%1,%2,%3};"
        : "+f"(d[0]), "+f"(d[1]), "+f"(d[2]), "+f"(d[3])
        : "r"(a[0]), "r"(a[1]), "r"(a[2]), "r"(a[3]), "r"(b[0]), "r"(b[1]));
}

// ================= grid build =================
__global__ void k_init_pg() {
    int i = blockIdx.x * blockDim.x + threadIdx.x;
    if (i < RESP*RESP*RESP) g_pg[i] = -1;
}
__global__ void k_scatter(const int* __restrict__ coords) {
    int i = blockIdx.x * blockDim.x + threadIdx.x;
    if (i < NP) g_pg[(coords[i*3]*RESP + coords[i*3+1])*RESP + coords[i*3+2]] = i;
}

// ================= group norm =================
template<bool SECOND>
__global__ void k_stats1(const float* __restrict__ xin, int nrows, int nsl) {
    const float* x = SECOND ? g_out1 : xin;
    int g = blockIdx.x, sl = blockIdx.y;
    int per = nrows / nsl, r0 = sl * per;
    float s = 0.f, q = 0.f;
    for (int r = r0 + threadIdx.x; r < r0 + per; r += blockDim.x) {
        float4 v = *reinterpret_cast<const float4*>(x + r*CH + g*4);
        s += (v.x + v.y) + (v.z + v.w);
        q += (v.x*v.x + v.y*v.y) + (v.z*v.z + v.w*v.w);
    }
    __shared__ float ss[256], sq[256];
    ss[threadIdx.x] = s; sq[threadIdx.x] = q;
    __syncthreads();
    for (int st = 128; st > 0; st >>= 1) {
        if (threadIdx.x < st) { ss[threadIdx.x] += ss[threadIdx.x+st]; sq[threadIdx.x] += sq[threadIdx.x+st]; }
        __syncthreads();
    }
    if (threadIdx.x == 0) { g_ps[g][sl] = ss[0]; g_pq[g][sl] = sq[0]; }
}
__global__ void k_stats2(int nsl) {
    int g = blockIdx.x, t = threadIdx.x;
    float s = (t < nsl) ? g_ps[g][t] : 0.f;
    float q = (t < nsl) ? g_pq[g][t] : 0.f;
#pragma unroll
    for (int o = 16; o > 0; o >>= 1) {
        s += __shfl_xor_sync(0xffffffff, s, o);
        q += __shfl_xor_sync(0xffffffff, q, o);
    }
    if (t == 0) { g_sum[g] = s; g_sq[g] = q; }
}
template<bool SECOND>
__global__ void k_gnsilu(const float* __restrict__ xin,
                         const float* __restrict__ gamma, const float* __restrict__ beta,
                         float invcnt, int n4) {
    int idx = blockIdx.x * blockDim.x + threadIdx.x;
    if (idx >= n4) return;
    const float* x = SECOND ? g_out1 : xin;
    float* outp    = SECOND ? g_h2   : g_h1;
    int g = idx & 31;
    float mean = g_sum[g] * invcnt;
    float var  = g_sq[g] * invcnt - mean * mean;
    float inv  = rsqrtf(var + EPSV);
    float4 v  = reinterpret_cast<const float4*>(x)[idx];
    float4 ga = reinterpret_cast<const float4*>(gamma)[g];
    float4 be = reinterpret_cast<const float4*>(beta)[g];
    float4 o; float y;
    y = (v.x - mean)*inv*ga.x + be.x; o.x = tf32r(y / (1.f + expf(-y)));
    y = (v.y - mean)*inv*ga.y + be.y; o.y = tf32r(y / (1.f + expf(-y)));
    y = (v.z - mean)*inv*ga.z + be.z; o.z = tf32r(y / (1.f + expf(-y)));
    y = (v.w - mean)*inv*ga.w + be.w; o.w = tf32r(y / (1.f + expf(-y)));
    reinterpret_cast<float4*>(outp)[idx] = o;
}

// ================= weight preprocessing: transpose to [mat][n][k] + tf32 round =================
__global__ void k_buildM1s(const float* __restrict__ W1) {
    int idx = blockIdx.x * blockDim.x + threadIdx.x;
    if (idx >= 64*CH*CH) return;
    int m = idx >> 14, rest = idx & 16383;
    int n = rest >> 7, kk = rest & 127;
    int k = m >> 3, j = m & 7;
    int s[3], cnt[3];
#pragma unroll
    for (int a = 0; a < 3; a++) {
        int o  = (k >> (2 - a)) & 1;
        int eb = (j >> (2 - a)) & 1;
        cnt[a] = 1 + (o ^ eb);
        s[a]   = -1 + eb * (1 + o);
    }
    float acc = 0.f;
    for (int d0 = 0; d0 < cnt[0]; d0++)
        for (int d1 = 0; d1 < cnt[1]; d1++)
            for (int d2 = 0; d2 < cnt[2]; d2++) {
                int k27 = ((s[0]+d0+1)*3 + (s[1]+d1+1))*3 + (s[2]+d2+1);
                acc += W1[k27*CH*CH + kk*CH + n];
            }
    g_M1s[idx] = tf32r(acc);
}
__global__ void k_buildW2s(const float* __restrict__ W2) {
    int idx = blockIdx.x * blockDim.x + threadIdx.x;
    if (idx >= 27*CH*CH) return;
    int m = idx >> 14, rest = idx & 16383;
    int n = rest >> 7, kk = rest & 127;
    g_W2s[idx] = tf32r(W2[m*CH*CH + kk*CH + n]);
}

// ================= tf32 mma conv kernels =================
// CTA: 256 rows x 128 cols, 16 warps (4m x 4n), warp tile 64x32.
// 3-stage cp.async pipeline, BK=16, row pitch 20 floats.
#define ROW_P  80
#define STG_A  20480     // 256 rows * 80 B
#define STG_B  10240     // 128 rows * 80 B
#define TILE_M 256

template<int NTAPS, bool ISC2>
__global__ __launch_bounds__(512, 1)
void k_convmma(const int* __restrict__ coords, const float* __restrict__ bias,
               const float* __restrict__ feats, float* __restrict__ dout) {
    extern __shared__ char dsm[];
    uint32_t smA = smem_u32(dsm);
    uint32_t smB = smA + 3*STG_A;
    int* snb = (int*)(dsm + 3*STG_A + 3*STG_B);

    const float* hsrc = ISC2 ? g_h2  : g_h1;
    const float* Wp   = ISC2 ? g_W2s : g_M1s;
    float* outp       = ISC2 ? dout  : g_out1;

    int tid = threadIdx.x, lane = tid & 31, wid = tid >> 5;
    int wm = wid & 3, wn = wid >> 2;
    int bx = blockIdx.x, ko = blockIdx.y;
    const int matBase = ISC2 ? 0 : ko*8;

    // ---- neighbor precompute ----
    for (int t = tid; t < NTAPS*TILE_M; t += 512) {
        int tap = t >> 8, row = t & (TILE_M-1);
        int nb = -1;
        if (ISC2) {
            int grow = bx*TILE_M + row;
            int pi = grow >> 3, k8 = grow & 7;
            int f0 = 2*coords[pi*3+0] + ((k8 >> 2) & 1) + (tap/9 - 1);
            int f1 = 2*coords[pi*3+1] + ((k8 >> 1) & 1) + ((tap/3) % 3 - 1);
            int f2 = 2*coords[pi*3+2] + (k8 & 1)        + (tap % 3 - 1);
            if ((unsigned)f0 < RESF && (unsigned)f1 < RESF && (unsigned)f2 < RESF) {
                int p = g_pg[((f0 >> 1)*RESP + (f1 >> 1))*RESP + (f2 >> 1)];
                if (p >= 0) nb = p*8 + (((f0 & 1) << 2) | ((f1 & 1) << 1) | (f2 & 1));
            }
        } else {
            int p = bx*TILE_M + row;
            int q0 = coords[p*3+0] + ((ko >> 2) & 1) - 1 + ((tap >> 2) & 1);
            int q1 = coords[p*3+1] + ((ko >> 1) & 1) - 1 + ((tap >> 1) & 1);
            int q2 = coords[p*3+2] + (ko & 1)        - 1 + (tap & 1);
            if ((unsigned)q0 < RESP && (unsigned)q1 < RESP && (unsigned)q2 < RESP)
                nb = g_pg[(q0*RESP + q1)*RESP + q2];
        }
        snb[t] = nb;
    }
    __syncthreads();

    // loader coords: A: 2 threads/row, 2 cp16 each; B: 4 threads/row, 1 cp16 each
    const int lrow = tid >> 1, lhalf = tid & 1;
    const int brow = tid >> 2, bq = tid & 3;

    // ldmatrix bases (stage 0)
    uint32_t Abase = smA + (uint32_t)((wm*64 + ((lane>>3)&1)*8 + (lane&7))*ROW_P + ((lane>>4)&1)*16);
    uint32_t Bbase = smB + (uint32_t)((wn*32 + ((lane>>4)&1)*8 + (lane&7))*ROW_P + ((lane>>3)&1)*16);

    float acc[4][4][4];
#pragma unroll
    for (int mt = 0; mt < 4; mt++)
#pragma unroll
        for (int nt = 0; nt < 4; nt++)
#pragma unroll
            for (int c = 0; c < 4; c++) acc[mt][nt][c] = 0.f;

    const int T = NTAPS * 8;

#define LOAD_STAGE(S, BUF) do { \
        int tap_ = (S) >> 3, c0_ = ((S) & 7) * 16; \
        int src_ = snb[tap_*TILE_M + lrow]; \
        uint32_t ssz_ = src_ >= 0 ? 16u : 0u; \
        const float* ap_ = hsrc + (src_ < 0 ? 0 : src_)*CH + c0_ + lhalf*8; \
        uint32_t ad_ = smA + (BUF)*STG_A + lrow*ROW_P + lhalf*32; \
        cp16(ad_, ap_, ssz_); cp16(ad_ + 16, ap_ + 4, ssz_); \
        const float* bp_ = Wp + ((matBase + tap_)*128 + brow)*128 + c0_ + bq*4; \
        uint32_t bd_ = smB + (BUF)*STG_B + brow*ROW_P + bq*16; \
        cp16(bd_, bp_, 16u); \
        cp_commit(); \
    } while (0)

    LOAD_STAGE(0, 0);
    LOAD_STAGE(1, 1);

    int sbuf = 0;
    for (int s = 0; s < T; s++) {
        if (s + 2 < T) CP_WAIT(1); else CP_WAIT(0);
        __syncthreads();
        if (s + 2 < T) {
            int buf2 = sbuf + 2; if (buf2 >= 3) buf2 -= 3;
            LOAD_STAGE(s + 2, buf2);
        }
        uint32_t ao = sbuf*STG_A, bo = sbuf*STG_B;
#pragma unroll
        for (int ks = 0; ks < 2; ks++) {
            uint32_t kb = ks * 32;
            uint32_t a[4][4];
#pragma unroll
            for (int mt = 0; mt < 4; mt++) ldsm4(a[mt], Abase + ao + kb + mt*16*ROW_P);
            uint32_t b[2][4];
#pragma unroll
            for (int p = 0; p < 2; p++) ldsm4(b[p], Bbase + bo + kb + p*16*ROW_P);
#pragma unroll
            for (int mt = 0; mt < 4; mt++)
#pragma unroll
                for (int nt = 0; nt < 4; nt++)
                    mma_tf32(acc[mt][nt], a[mt], b[nt >> 1] + (nt & 1)*2);
        }
        sbuf++; if (sbuf == 3) sbuf = 0;
    }
#undef LOAD_STAGE

    // ---- epilogue: register -> gmem, fused bias (+residual) ----
#pragma unroll
    for (int mt = 0; mt < 4; mt++) {
        int rl = wm*64 + mt*16 + (lane >> 2);
#pragma unroll
        for (int half = 0; half < 2; half++) {
            int row = rl + half*8;
            int orow, prow;
            if (ISC2) { orow = bx*TILE_M + row; prow = orow >> 3; }
            else      { orow = (bx*TILE_M + row)*8 + ko; prow = -1; }
#pragma unroll
            for (int nt = 0; nt < 4; nt++) {
                int col = wn*32 + nt*8 + (lane & 3)*2;
                float2 bb = *reinterpret_cast<const float2*>(bias + col);
                float vx = acc[mt][nt][half*2 + 0] + bb.x;
                float vy = acc[mt][nt][half*2 + 1] + bb.y;
                if (ISC2) {
                    float2 rr = *reinterpret_cast<const float2*>(feats + prow*CH + col);
                    vx += rr.x; vy += rr.y;
                }
                float2 o; o.x = vx; o.y = vy;
                *reinterpret_cast<float2*>(outp + orow*CH + col) = o;
            }
        }
    }
}

// ================= launch =================
extern "C" void kernel_launch(void* const* d_in, const int* in_sizes, int n_in,
                              void* d_out, int out_size) {
    const float* feats  = (const float*)d_in[0];
    const float* gamma1 = (const float*)d_in[1];
    const float* beta1  = (const float*)d_in[2];
    const float* W1     = (const float*)d_in[3];
    const float* b1     = (const float*)d_in[4];
    const float* gamma2 = (const float*)d_in[5];
    const float* beta2  = (const float*)d_in[6];
    const float* W2     = (const float*)d_in[7];
    const float* b2     = (const float*)d_in[8];
    const int*   coords = (const int*)d_in[9];
    float* out = (float*)d_out;

    const int smemBase = 3*STG_A + 3*STG_B;         // 92160
    const int smem1 = smemBase + 8*TILE_M*4;        // 100352
    const int smem2 = smemBase + 27*TILE_M*4;       // 119808
    cudaFuncSetAttribute(k_convmma<8,false>, cudaFuncAttributeMaxDynamicSharedMemorySize, smem1);
    cudaFuncSetAttribute(k_convmma<27,true>, cudaFuncAttributeMaxDynamicSharedMemorySize, smem2);

    k_init_pg<<<128, 256>>>();
    k_scatter<<<32, 256>>>(coords);
    k_buildM1s<<<4096, 256>>>(W1);
    k_buildW2s<<<1728, 256>>>(W2);

    // GN1 + SiLU -> g_h1 (tf32-rounded)
    k_stats1<false><<<dim3(32, 8), 256>>>(feats, NP, 8);
    k_stats2<<<32, 32>>>(8);
    k_gnsilu<false><<<(NP*32 + 255)/256, 256>>>(feats, gamma1, beta1, 1.f/(NP*4), NP*32);

    // conv1 (parent-level, aggregated taps) -> g_out1
    k_convmma<8,false><<<dim3(NP/TILE_M, 8), 512, smem1>>>(coords, b1, nullptr, nullptr);

    // GN2 + SiLU -> g_h2 (tf32-rounded)
    k_stats1<true><<<dim3(32, 32), 256>>>(nullptr, NF, 32);
    k_stats2<<<32, 32>>>(32);
    k_gnsilu<true><<<(NF*32 + 255)/256, 256>>>(nullptr, gamma2, beta2, 1.f/(NF*4), NF*32);

    // conv2 (fine-level, 27 taps) + bias + residual -> out
    k_convmma<27,true><<<NF/TILE_M, 512, smem2>>>(coords, b2, feats, out);
}